// round 17
// baseline (speedup 1.0000x reference)
#include <cuda_runtime.h>
#include <cuda_fp16.h>
#include <cuda_bf16.h>
#include <stdint.h>

#define NN 40000
#define EMAX 640000
#define DD 128
#define SCAN_BLK 256
#define PGRID 296                   // persistent GEMM CTAs (2/SM at 96KB smem)
#define THREADS_G 256
#define TILES_MAX 625               // NN / 64 exactly

typedef unsigned long long ull;
typedef unsigned int u32;

// Scratch (allocation-free rule: __device__ globals)
__device__ __align__(16) __half g_z[NN * DD];       // z fp16: halves gather traffic
__device__ __align__(16) __nv_bfloat16 g_Ahi[TILES_MAX * 64 * DD];  // h split-bf16 tiles
__device__ __align__(16) __nv_bfloat16 g_Alo[TILES_MAX * 64 * DD];
__device__ int g_deg[NN];
__device__ int g_rowptr[NN + 1];
__device__ int g_ctr[NN];
__device__ int g_csrcol[EMAX];
__device__ int g_partial[1024];
__device__ int g_is64;
__device__ int g_tctr[4];                           // per-GEMM dynamic tile counters
__device__ __align__(16) __nv_bfloat16 g_Whi[3][16384];  // pre-swizzled W^T hi
__device__ __align__(16) __nv_bfloat16 g_Wlo[3][16384];  // pre-swizzled W^T lo

// ---------------------------------------------------------------------------
// Swizzled offset inside a [rows][128 cols] bf16 tile, pitch 256B.
// 16B chunk c of row r goes to chunk c ^ (r & 7) -> conflict-free ldmatrix.
// ---------------------------------------------------------------------------
__host__ __device__ __forceinline__ u32 tile_off(int r, int c16) {
    return (u32)r * 256u + (u32)((c16 ^ (r & 7)) << 4);
}

// ---------------------------------------------------------------------------
// mma.sync / ldmatrix / cp.async helpers (plain sm_103-legal)
// ---------------------------------------------------------------------------
__device__ __forceinline__ void mma16816(float* d, const u32* a, const u32* b) {
    asm volatile("mma.sync.aligned.m16n8k16.row.col.f32.bf16.bf16.f32 "
                 "{%0,%1,%2,%3}, {%4,%5,%6,%7}, {%8,%9}, {%0,%1,%2,%3};"
                 : "+f"(d[0]), "+f"(d[1]), "+f"(d[2]), "+f"(d[3])
                 : "r"(a[0]), "r"(a[1]), "r"(a[2]), "r"(a[3]),
                   "r"(b[0]), "r"(b[1]));
}
__device__ __forceinline__ void ldm_x4(u32* r, u32 addr) {
    asm volatile("ldmatrix.sync.aligned.m8n8.x4.shared.b16 {%0,%1,%2,%3}, [%4];"
                 : "=r"(r[0]), "=r"(r[1]), "=r"(r[2]), "=r"(r[3]) : "r"(addr));
}
__device__ __forceinline__ u32 smem_u32(const void* p) {
    u32 a;
    asm("{ .reg .u64 t; cvta.to.shared.u64 t, %1; cvt.u32.u64 %0, t; }" : "=r"(a) : "l"(p));
    return a;
}
#define CP_ASYNC16(d, s) asm volatile("cp.async.cg.shared.global [%0], [%1], 16;" :: "r"(d), "l"(s))
#define CP_COMMIT()      asm volatile("cp.async.commit_group;" ::: "memory")
#define CP_WAIT0()       asm volatile("cp.async.wait_group 0;" ::: "memory")

__device__ __forceinline__ void split_bf16(float v, unsigned short& h, unsigned short& lo) {
    __nv_bfloat16 hb = __float2bfloat16(v);
    h = __bfloat16_as_ushort(hb);
    lo = __bfloat16_as_ushort(__float2bfloat16(v - __bfloat162float(hb)));
}

// ---------------------------------------------------------------------------
// W conversion: fp32 W [k][n] -> split-bf16 W^T tiles [n row][k col], swizzled.
// DO_RESET: block 0 also resets the dynamic tile counters (main-stream use).
// ---------------------------------------------------------------------------
__global__ void wconv_kernel(const float* __restrict__ W,
                             __nv_bfloat16* __restrict__ hi,
                             __nv_bfloat16* __restrict__ lo,
                             int do_reset, int start) {
    if (do_reset && blockIdx.x == 0 && threadIdx.x < 4) g_tctr[threadIdx.x] = start;
    int idx = blockIdx.x * 256 + threadIdx.x;
    if (idx >= 16384) return;
    int k = idx >> 7, nn = idx & 127;
    unsigned short hs, ls;
    split_bf16(W[idx], hs, ls);
    u32 off = tile_off(nn, k >> 3) + (u32)(k & 7) * 2u;
    *(unsigned short*)((char*)hi + off) = hs;
    *(unsigned short*)((char*)lo + off) = ls;
}

// ---------------------------------------------------------------------------
// Persistent tensor-core GEMM: C[n,128] = A @ W (+bias).
// 64x128x128 tile; 256 threads = 8 warps in 2(M) x 4(N); warp: 32M x 32N.
// 96KB smem -> 2 CTAs/SM (co-resident CTA hides single-buffer load latency).
// LOAD_SPLIT=1: A from pre-split tiles via cp.async, issued post-MMA so the
//               copy overlaps the epilogue. LOAD_SPLIT=0: fp32 load + convert.
// SPLIT_OUT=1: epilogue also writes split-bf16 tiles of the output (fp32 path).
// Smem: W hi 32K | W lo 32K | A hi 16K | A lo 16K | queue slots.
// ---------------------------------------------------------------------------
#define GEMM_SMEM (98304 + 32)

template <int LOAD_SPLIT, int HALF_OUT, int SPLIT_OUT>
__global__ __launch_bounds__(THREADS_G, 2)
void tgemm_kernel(const float* __restrict__ Af32,
                  const __nv_bfloat16* __restrict__ Ahi_g,
                  const __nv_bfloat16* __restrict__ Alo_g,
                  const __nv_bfloat16* __restrict__ Whi,
                  const __nv_bfloat16* __restrict__ Wlo,
                  const float* __restrict__ bias, void* __restrict__ Cv,
                  __nv_bfloat16* __restrict__ Ohi, __nv_bfloat16* __restrict__ Olo,
                  int n, int ntiles, int slot) {
    extern __shared__ char smem[];
    const u32 sb = smem_u32(smem);
    const u32 aAh = sb + 65536, aAl = sb + 81920;
    int* nextp = (int*)(smem + 98304);

    const int tid = threadIdx.x;
    const int wid = tid >> 5;
    const int l   = tid & 31;
    const int R0  = (wid >> 2) * 32;     // 0 or 32
    const int N0  = (wid & 3) * 32;      // 0,32,64,96

    // ldmatrix lane address components
    const int ar = (l & 15);
    const int ac = (l >> 4);
    const int br = (l & 7) + ((l >> 4) & 1) * 8;
    const int bc = (l >> 3) & 1;

    // Prologue: copy pre-swizzled W hi/lo (2048 uint4 each, 8 per thread)
    {
        const uint4* shp = (const uint4*)Whi;
        const uint4* slp = (const uint4*)Wlo;
        uint4* dh = (uint4*)smem;
        uint4* dl = (uint4*)(smem + 32768);
        #pragma unroll
        for (int i = 0; i < 8; ++i) {
            dh[tid + i * 256] = shp[tid + i * 256];
            dl[tid + i * 256] = slp[tid + i * 256];
        }
    }

    // Bias pairs per lane (fp32 out path)
    float2 bv[4];
    #pragma unroll
    for (int nt = 0; nt < 4; ++nt) bv[nt] = make_float2(0.f, 0.f);
    if (!HALF_OUT && bias) {
        #pragma unroll
        for (int nt = 0; nt < 4; ++nt)
            bv[nt] = *(const float2*)(bias + N0 + nt * 8 + 2 * (l & 3));
    }

    int t_cur = blockIdx.x;

    // First A tile into the (single) buffer
    if (t_cur < ntiles) {
        if (LOAD_SPLIT) {
            const char* shp = (const char*)Ahi_g + (size_t)t_cur * 16384;
            const char* slp = (const char*)Alo_g + (size_t)t_cur * 16384;
            #pragma unroll
            for (int i = 0; i < 4; ++i) {
                CP_ASYNC16(aAh + (u32)(tid + i * 256) * 16u, shp + (tid + i * 256) * 16);
                CP_ASYNC16(aAl + (u32)(tid + i * 256) * 16u, slp + (tid + i * 256) * 16);
            }
        } else {
            #pragma unroll
            for (int i = 0; i < 8; ++i) {
                int e4 = tid + i * 256;
                int r = e4 >> 5, c4 = e4 & 31;
                int row = t_cur * 64 + r;
                float4 v = make_float4(0.f, 0.f, 0.f, 0.f);
                if (row < n) v = *(const float4*)(Af32 + (size_t)row * DD + c4 * 4);
                float f[4] = {v.x, v.y, v.z, v.w};
                unsigned short hs[4], ls[4];
                #pragma unroll
                for (int j = 0; j < 4; ++j) split_bf16(f[j], hs[j], ls[j]);
                u32 off = tile_off(r, c4 >> 1) + (u32)(c4 & 1) * 8u;
                *(ushort4*)(smem + 65536 + off) = make_ushort4(hs[0], hs[1], hs[2], hs[3]);
                *(ushort4*)(smem + 81920 + off) = make_ushort4(ls[0], ls[1], ls[2], ls[3]);
            }
        }
    }
    CP_COMMIT();
    if (tid == 0) nextp[0] = atomicAdd(&g_tctr[slot], 1);
    CP_WAIT0();
    __syncthreads();
    int parity = 0;
    int t_next = nextp[0];

    while (t_cur < ntiles) {
        // ---- MMA on the A buffer ----
        float acc[2][4][4];
        #pragma unroll
        for (int mt = 0; mt < 2; ++mt)
            #pragma unroll
            for (int nt = 0; nt < 4; ++nt)
                #pragma unroll
                for (int q = 0; q < 4; ++q) acc[mt][nt][q] = 0.f;

        #pragma unroll
        for (int kk = 0; kk < 8; ++kk) {
            u32 ah[2][4], al[2][4];
            #pragma unroll
            for (int mt = 0; mt < 2; ++mt) {
                u32 off = tile_off(R0 + mt * 16 + ar, 2 * kk + ac);
                ldm_x4(ah[mt], aAh + off);
                ldm_x4(al[mt], aAl + off);
            }
            #pragma unroll
            for (int np = 0; np < 2; ++np) {
                u32 boff = tile_off(N0 + np * 16 + br, 2 * kk + bc);
                u32 bh[4], bl[4];
                ldm_x4(bh, sb + boff);
                ldm_x4(bl, sb + 32768 + boff);
                #pragma unroll
                for (int mt = 0; mt < 2; ++mt) {
                    mma16816(acc[mt][2 * np + 0], ah[mt], bh + 0);
                    mma16816(acc[mt][2 * np + 0], ah[mt], bl + 0);
                    mma16816(acc[mt][2 * np + 0], al[mt], bh + 0);
                    mma16816(acc[mt][2 * np + 1], ah[mt], bh + 2);
                    mma16816(acc[mt][2 * np + 1], ah[mt], bl + 2);
                    mma16816(acc[mt][2 * np + 1], al[mt], bh + 2);
                }
            }
        }
        __syncthreads();   // all warps done reading the A buffer

        // ---- Start next A tile load (overlaps the epilogue below) ----
        if (t_next < ntiles) {
            if (LOAD_SPLIT) {
                const char* shp = (const char*)Ahi_g + (size_t)t_next * 16384;
                const char* slp = (const char*)Alo_g + (size_t)t_next * 16384;
                #pragma unroll
                for (int i = 0; i < 4; ++i) {
                    CP_ASYNC16(aAh + (u32)(tid + i * 256) * 16u, shp + (tid + i * 256) * 16);
                    CP_ASYNC16(aAl + (u32)(tid + i * 256) * 16u, slp + (tid + i * 256) * 16);
                }
                CP_COMMIT();
            } else {
                #pragma unroll
                for (int i = 0; i < 8; ++i) {
                    int e4 = tid + i * 256;
                    int r = e4 >> 5, c4 = e4 & 31;
                    int row = t_next * 64 + r;
                    float4 v = make_float4(0.f, 0.f, 0.f, 0.f);
                    if (row < n) v = *(const float4*)(Af32 + (size_t)row * DD + c4 * 4);
                    float f[4] = {v.x, v.y, v.z, v.w};
                    unsigned short hs[4], ls[4];
                    #pragma unroll
                    for (int j = 0; j < 4; ++j) split_bf16(f[j], hs[j], ls[j]);
                    u32 off = tile_off(r, c4 >> 1) + (u32)(c4 & 1) * 8u;
                    *(ushort4*)(smem + 65536 + off) = make_ushort4(hs[0], hs[1], hs[2], hs[3]);
                    *(ushort4*)(smem + 81920 + off) = make_ushort4(ls[0], ls[1], ls[2], ls[3]);
                }
            }
        }
        if (tid == 0) nextp[parity ^ 1] = atomicAdd(&g_tctr[slot], 1);

        // ---- Epilogue for t_cur (registers only; overlaps cp.async) ----
        #pragma unroll
        for (int mt = 0; mt < 2; ++mt) {
            int r1 = t_cur * 64 + R0 + mt * 16 + (l >> 2);
            int r2 = r1 + 8;
            #pragma unroll
            for (int nt = 0; nt < 4; ++nt) {
                int col = N0 + nt * 8 + 2 * (l & 3);
                const float* d = acc[mt][nt];
                int rows[2] = {r1, r2};
                #pragma unroll
                for (int h2 = 0; h2 < 2; ++h2) {
                    int row = rows[h2];
                    if (row >= n) continue;
                    float v0 = d[2 * h2 + 0], v1 = d[2 * h2 + 1];
                    if (HALF_OUT) {
                        *(__half2*)((__half*)Cv + (size_t)row * DD + col) =
                            __floats2half2_rn(v0, v1);
                    } else {
                        v0 += bv[nt].x; v1 += bv[nt].y;
                        *(float2*)((float*)Cv + (size_t)row * DD + col) = make_float2(v0, v1);
                        if (SPLIT_OUT) {
                            unsigned short h0, l0, h1, l1;
                            split_bf16(v0, h0, l0);
                            split_bf16(v1, h1, l1);
                            size_t o = (size_t)(row >> 6) * 16384 +
                                       tile_off(row & 63, col >> 3) + (col & 7) * 2;
                            *(u32*)((char*)Ohi + o) = (u32)h0 | ((u32)h1 << 16);
                            *(u32*)((char*)Olo + o) = (u32)l0 | ((u32)l1 << 16);
                        }
                    }
                }
            }
        }

        CP_WAIT0();
        __syncthreads();
        t_cur = t_next;
        t_next = nextp[parity ^ 1];
        parity ^= 1;
    }
}

// ---------------------------------------------------------------------------
// Detect int64 vs int32 edge_index: one warp, 128 values, ballot.
// ---------------------------------------------------------------------------
__global__ void detect_idx_kernel(const long long* __restrict__ p) {
    int t = threadIdx.x;
    int bad = 0;
    #pragma unroll
    for (int i = 0; i < 4; ++i) {
        long long v = p[t + i * 32];
        bad |= (v < 0 || v >= NN);
    }
    unsigned m = __ballot_sync(0xffffffffu, bad);
    if (t == 0) g_is64 = (m == 0);
}

__device__ __forceinline__ int load_idx(const void* p, int i) {
    return g_is64 ? (int)((const long long*)p)[i] : ((const int*)p)[i];
}

// ---------------------------------------------------------------------------
// CSR construction: zero -> histogram -> 3-phase scan -> fill
// ---------------------------------------------------------------------------
__global__ void zero_deg_kernel(int* __restrict__ deg, int n) {
    int i = blockIdx.x * blockDim.x + threadIdx.x;
    if (i < n) deg[i] = 0;
}

__global__ void hist_kernel(const void* __restrict__ eidx, int* __restrict__ deg, int E) {
    int e = blockIdx.x * blockDim.x + threadIdx.x;
    if (e >= E) return;
    atomicAdd(&deg[load_idx(eidx, e)], 1);
}

__global__ void scan_phase1(const int* __restrict__ deg, int* __restrict__ rowptr,
                            int* __restrict__ partial, int n) {
    __shared__ int sm[SCAN_BLK];
    const int t = threadIdx.x;
    const int i = blockIdx.x * SCAN_BLK + t;
    int v = (i < n) ? deg[i] : 0;
    sm[t] = v;
    __syncthreads();
    #pragma unroll
    for (int off = 1; off < SCAN_BLK; off <<= 1) {
        int u = (t >= off) ? sm[t - off] : 0;
        __syncthreads();
        sm[t] += u;
        __syncthreads();
    }
    if (i < n) rowptr[i] = sm[t] - v;
    if (t == SCAN_BLK - 1) partial[blockIdx.x] = sm[t];
}

__global__ void scan_phase2(int* __restrict__ partial, int nb,
                            int* __restrict__ rowptr, int n, int E) {
    __shared__ int sm[1024];
    const int t = threadIdx.x;
    int v = (t < nb) ? partial[t] : 0;
    sm[t] = v;
    __syncthreads();
    #pragma unroll
    for (int off = 1; off < 1024; off <<= 1) {
        int u = (t >= off) ? sm[t - off] : 0;
        __syncthreads();
        sm[t] += u;
        __syncthreads();
    }
    if (t < nb) partial[t] = sm[t] - v;
    if (t == 0) rowptr[n] = E;
}

__global__ void scan_phase3(int* __restrict__ rowptr, int* __restrict__ ctr,
                            const int* __restrict__ partial, int n) {
    int i = blockIdx.x * SCAN_BLK + threadIdx.x;
    if (i < n) {
        int v = rowptr[i] + partial[blockIdx.x];
        rowptr[i] = v;
        ctr[i] = v;
    }
}

__global__ void fill_kernel(const void* __restrict__ eidx, int* __restrict__ ctr,
                            int* __restrict__ csrcol, int E) {
    int e = blockIdx.x * blockDim.x + threadIdx.x;
    if (e >= E) return;
    int row = load_idx(eidx, e);
    int col = load_idx(eidx, E + e);
    int pos = atomicAdd(&ctr[row], 1);
    csrcol[pos] = col;
}

// ---------------------------------------------------------------------------
// Fused gather-aggregate + relu + residual: one warp per node, z in fp16.
// SPLIT_OUT=1 additionally writes the updated h as split-bf16 tiles.
// ---------------------------------------------------------------------------
template <int SPLIT_OUT>
__global__ __launch_bounds__(256)
void gather_relu_res_kernel(const int* __restrict__ rowptr,
                            const int* __restrict__ csrcol,
                            const __half* __restrict__ z,
                            float* __restrict__ h,
                            const float* __restrict__ b,
                            __nv_bfloat16* __restrict__ Ohi,
                            __nv_bfloat16* __restrict__ Olo, int n) {
    int warp = (blockIdx.x * blockDim.x + threadIdx.x) >> 5;
    int lane = threadIdx.x & 31;
    if (warp >= n) return;

    const int s = rowptr[warp];
    const int e = rowptr[warp + 1];
    const int off = lane * 4;

    float4 acc = make_float4(0.f, 0.f, 0.f, 0.f);

    int j = s;
    for (; j + 4 <= e; j += 4) {
        int c0 = csrcol[j + 0];
        int c1 = csrcol[j + 1];
        int c2 = csrcol[j + 2];
        int c3 = csrcol[j + 3];
        __half2 p0[2], p1[2], p2[2], p3[2];
        *reinterpret_cast<uint2*>(p0) = *reinterpret_cast<const uint2*>(z + (size_t)c0 * DD + off);
        *reinterpret_cast<uint2*>(p1) = *reinterpret_cast<const uint2*>(z + (size_t)c1 * DD + off);
        *reinterpret_cast<uint2*>(p2) = *reinterpret_cast<const uint2*>(z + (size_t)c2 * DD + off);
        *reinterpret_cast<uint2*>(p3) = *reinterpret_cast<const uint2*>(z + (size_t)c3 * DD + off);
        float2 f;
        f = __half22float2(p0[0]); acc.x += f.x; acc.y += f.y;
        f = __half22float2(p0[1]); acc.z += f.x; acc.w += f.y;
        f = __half22float2(p1[0]); acc.x += f.x; acc.y += f.y;
        f = __half22float2(p1[1]); acc.z += f.x; acc.w += f.y;
        f = __half22float2(p2[0]); acc.x += f.x; acc.y += f.y;
        f = __half22float2(p2[1]); acc.z += f.x; acc.w += f.y;
        f = __half22float2(p3[0]); acc.x += f.x; acc.y += f.y;
        f = __half22float2(p3[1]); acc.z += f.x; acc.w += f.y;
    }
    for (; j < e; ++j) {
        int c = csrcol[j];
        __half2 p[2];
        *reinterpret_cast<uint2*>(p) = *reinterpret_cast<const uint2*>(z + (size_t)c * DD + off);
        float2 f;
        f = __half22float2(p[0]); acc.x += f.x; acc.y += f.y;
        f = __half22float2(p[1]); acc.z += f.x; acc.w += f.y;
    }

    float4 bvv = *reinterpret_cast<const float4*>(b + off);
    float4 hv = *reinterpret_cast<float4*>(h + (size_t)warp * DD + off);
    hv.x += fmaxf(acc.x + bvv.x, 0.f);
    hv.y += fmaxf(acc.y + bvv.y, 0.f);
    hv.z += fmaxf(acc.z + bvv.z, 0.f);
    hv.w += fmaxf(acc.w + bvv.w, 0.f);
    *reinterpret_cast<float4*>(h + (size_t)warp * DD + off) = hv;

    if (SPLIT_OUT) {
        float v[4] = {hv.x, hv.y, hv.z, hv.w};
        unsigned short hs[4], ls[4];
        #pragma unroll
        for (int q = 0; q < 4; ++q) split_bf16(v[q], hs[q], ls[q]);
        size_t o = (size_t)(warp >> 6) * 16384 +
                   tile_off(warp & 63, off >> 3) + (off & 7) * 2;
        *(ushort4*)((char*)Ohi + o) = make_ushort4(hs[0], hs[1], hs[2], hs[3]);
        *(ushort4*)((char*)Olo + o) = make_ushort4(ls[0], ls[1], ls[2], ls[3]);
    }
}

// ---------------------------------------------------------------------------
extern "C" void kernel_launch(void* const* d_in, const int* in_sizes, int n_in,
                              void* d_out, int out_size) {
    const float* x   = (const float*)d_in[0];
    const void*  eix = d_in[1];
    const float* W_t = (const float*)d_in[2];
    const float* b_t = (const float*)d_in[3];
    const float* W0  = (const float*)d_in[4];
    const float* b0  = (const float*)d_in[5];
    const float* W1  = (const float*)d_in[6];
    const float* b1  = (const float*)d_in[7];
    float* h = (float*)d_out;

    const int n = in_sizes[0] / DD;   // 40000
    const int E = in_sizes[1] / 2;    // 640000

    __half* z_ptr;
    int *deg_ptr, *rowptr_ptr, *ctr_ptr, *csrcol_ptr, *partial_ptr;
    __nv_bfloat16 *whi, *wlo, *ahi, *alo;
    cudaGetSymbolAddress((void**)&z_ptr, g_z);
    cudaGetSymbolAddress((void**)&deg_ptr, g_deg);
    cudaGetSymbolAddress((void**)&rowptr_ptr, g_rowptr);
    cudaGetSymbolAddress((void**)&ctr_ptr, g_ctr);
    cudaGetSymbolAddress((void**)&csrcol_ptr, g_csrcol);
    cudaGetSymbolAddress((void**)&partial_ptr, g_partial);
    cudaGetSymbolAddress((void**)&whi, g_Whi);
    cudaGetSymbolAddress((void**)&wlo, g_Wlo);
    cudaGetSymbolAddress((void**)&ahi, g_Ahi);
    cudaGetSymbolAddress((void**)&alo, g_Alo);

    cudaFuncSetAttribute(tgemm_kernel<0, 0, 1>,
                         cudaFuncAttributeMaxDynamicSharedMemorySize, GEMM_SMEM);
    cudaFuncSetAttribute(tgemm_kernel<1, 1, 0>,
                         cudaFuncAttributeMaxDynamicSharedMemorySize, GEMM_SMEM);

    const int ntiles = (n + 63) / 64;               // 625
    const int ggrid  = ntiles < PGRID ? ntiles : PGRID;
    const int edge_blocks = (E + 255) / 256;
    const int node_blocks = (n * 32 + 255) / 256;   // warp per node
    const int scan_blocks = (n + SCAN_BLK - 1) / SCAN_BLK;

    // Side stream (host objects only; replays execute the captured graph).
    cudaStream_t side;
    cudaStreamCreateWithFlags(&side, cudaStreamNonBlocking);
    cudaEvent_t evF, evW0, evJ, evW1;
    cudaEventCreateWithFlags(&evF, cudaEventDisableTiming);
    cudaEventCreateWithFlags(&evW0, cudaEventDisableTiming);
    cudaEventCreateWithFlags(&evJ, cudaEventDisableTiming);
    cudaEventCreateWithFlags(&evW1, cudaEventDisableTiming);

    cudaEventRecord(evF, 0);
    cudaStreamWaitEvent(side, evF, 0);

    // MAIN: W_t conversion (+ counter reset) directly, then GEMM_t.
    wconv_kernel<<<64, 256>>>(W_t, whi, wlo, 1, ggrid);              // main
    // SIDE: W0 first, then CSR build, then W1.
    wconv_kernel<<<64, 256, 0, side>>>(W0, whi + 16384, wlo + 16384, 0, 0);
    cudaEventRecord(evW0, side);
    tgemm_kernel<0, 0, 1><<<ggrid, THREADS_G, GEMM_SMEM>>>(
        x, nullptr, nullptr, whi, wlo, b_t, h, ahi, alo, n, ntiles, 0);  // main
    detect_idx_kernel<<<1, 32, 0, side>>>((const long long*)eix);
    zero_deg_kernel<<<(n + 255) / 256, 256, 0, side>>>(deg_ptr, n);
    hist_kernel<<<edge_blocks, 256, 0, side>>>(eix, deg_ptr, E);
    scan_phase1<<<scan_blocks, SCAN_BLK, 0, side>>>(deg_ptr, rowptr_ptr, partial_ptr, n);
    scan_phase2<<<1, 1024, 0, side>>>(partial_ptr, scan_blocks, rowptr_ptr, n, E);
    scan_phase3<<<scan_blocks, SCAN_BLK, 0, side>>>(rowptr_ptr, ctr_ptr, partial_ptr, n);
    fill_kernel<<<edge_blocks, 256, 0, side>>>(eix, ctr_ptr, csrcol_ptr, E);
    cudaEventRecord(evJ, side);
    wconv_kernel<<<64, 256, 0, side>>>(W1, whi + 2 * 16384, wlo + 2 * 16384, 0, 0);
    cudaEventRecord(evW1, side);

    // z = h @ W0 (fp16 out), A from split tiles
    cudaStreamWaitEvent(0, evW0, 0);
    tgemm_kernel<1, 1, 0><<<ggrid, THREADS_G, GEMM_SMEM>>>(
        nullptr, ahi, alo, whi + 16384, wlo + 16384, nullptr, z_ptr,
        nullptr, nullptr, n, ntiles, 1);

    // join: gathers need the CSR
    cudaStreamWaitEvent(0, evJ, 0);

    // layer 0: h += relu(gather(z) + b0); also refresh split-bf16 h tiles
    gather_relu_res_kernel<1><<<node_blocks, 256>>>(
        rowptr_ptr, csrcol_ptr, z_ptr, h, b0, ahi, alo, n);

    // layer 1
    cudaStreamWaitEvent(0, evW1, 0);
    tgemm_kernel<1, 1, 0><<<ggrid, THREADS_G, GEMM_SMEM>>>(
        nullptr, ahi, alo, whi + 2 * 16384, wlo + 2 * 16384, nullptr, z_ptr,
        nullptr, nullptr, n, ntiles, 2);
    gather_relu_res_kernel<0><<<node_blocks, 256>>>(
        rowptr_ptr, csrcol_ptr, z_ptr, h, b1, nullptr, nullptr, n);
}